// round 11
// baseline (speedup 1.0000x reference)
#include <cuda_runtime.h>
#include <cuda_bf16.h>
#include <math.h>

// Problem shape (fixed by the dataset): input [N, T] fp32, label [N] fp32.
static constexpr int N_ROWS = 8192;
static constexpr int T_COLS = 8192;

static constexpr int THREADS = 256;                             // per block
static constexpr int VECS_PER_THREAD = T_COLS / (THREADS * 4);  // 8 float4 each

// Scratch (no cudaMalloc allowed). Both are 0 at process start (static init)
// and are RESET by the last-arriving block each run, so every graph replay
// starts from a clean state.
__device__ unsigned long long g_acc_bits;   // double accumulator, as bits
__device__ unsigned int g_ticket;

// minBlocksPerMultiprocessor=6 caps the allocation at 42 regs (65536/6/256),
// restoring 6 blocks/SM. The hot path needs ~40; any spill pressure lands in
// the cold tid==0 epilogue where v[] is dead.
__global__ __launch_bounds__(THREADS, 6)
void loss_kernel(const float* __restrict__ in,
                 const float* __restrict__ label,
                 float* __restrict__ out) {
    const int row = blockIdx.x;
    const int tid = threadIdx.x;
    const size_t row_off = (size_t)row * T_COLS;
    const float4* rp = reinterpret_cast<const float4*>(in + row_off);

    __shared__ float s_red[THREADS / 32];
    __shared__ float s_max;
    __shared__ float s_sum;

    // ---- Stage the whole row slice into registers (coalesced float4).
    //      The block-max below consumes ALL of v[], forcing ptxas to
    //      front-batch the 8 LDG.128 (MLP_p1=8) — this saturates HBM.
    float4 v[VECS_PER_THREAD];
#pragma unroll
    for (int k = 0; k < VECS_PER_THREAD; k++) {
        v[k] = rp[tid + k * THREADS];
    }

    // ---- Thread-local max ----
    float m = -INFINITY;
#pragma unroll
    for (int k = 0; k < VECS_PER_THREAD; k++) {
        m = fmaxf(m, fmaxf(fmaxf(v[k].x, v[k].y), fmaxf(v[k].z, v[k].w)));
    }

    // ---- Block reduce max ----
#pragma unroll
    for (int off = 16; off > 0; off >>= 1)
        m = fmaxf(m, __shfl_xor_sync(0xFFFFFFFFu, m, off));
    if ((tid & 31) == 0) s_red[tid >> 5] = m;
    __syncthreads();
    if (tid < 32) {
        float mm = (tid < THREADS / 32) ? s_red[tid] : -INFINITY;
#pragma unroll
        for (int off = 4; off > 0; off >>= 1)
            mm = fmaxf(mm, __shfl_xor_sync(0xFFFFFFFFu, mm, off));
        if (tid == 0) s_max = mm;
    }
    __syncthreads();
    const float M = s_max;

    // ---- Sum of exp(x - M) : one MUFU per element, data already in regs ----
    float s = 0.0f;
#pragma unroll
    for (int k = 0; k < VECS_PER_THREAD; k++) {
        s += __expf(v[k].x - M);
        s += __expf(v[k].y - M);
        s += __expf(v[k].z - M);
        s += __expf(v[k].w - M);
    }
#pragma unroll
    for (int off = 16; off > 0; off >>= 1)
        s += __shfl_xor_sync(0xFFFFFFFFu, s, off);
    if ((tid & 31) == 0) s_red[tid >> 5] = s;
    __syncthreads();
    if (tid < 32) {
        float ss = (tid < THREADS / 32) ? s_red[tid] : 0.0f;
#pragma unroll
        for (int off = 4; off > 0; off >>= 1)
            ss += __shfl_xor_sync(0xFFFFFFFFu, ss, off);
        if (tid == 0) s_sum = ss;
    }
    __syncthreads();

    // ---- Thread 0 only: row loss -> double atomic; last block finalizes. ----
    if (tid == 0) {
        const float lse = M + __logf(s_sum);

        const float lab = label[row];
        const float pos = lab * (float)T_COLS - 1.0f;
        const int fl = (int)floorf(pos);
        const int ce = (int)ceilf(pos);

        // Replicate reference write ORDER (later writes overwrite earlier).
        int   cols[4];
        float vals[4];
        cols[0] = max(fl - 1, 0);          vals[0] = 0.1f;
        cols[1] = fl;                      vals[1] = (fl >= 1) ? 0.4f : 0.5f;
        cols[2] = min(ce + 1, T_COLS - 1); vals[2] = 0.1f;
        cols[3] = ce;                      vals[3] = (ce < T_COLS - 1) ? 0.4f : 0.5f;

        float wsum = 0.0f, dot = 0.0f;
#pragma unroll
        for (int i = 0; i < 4; i++) {
            bool alive = true;
#pragma unroll
            for (int j = i + 1; j < 4; j++)
                if (cols[j] == cols[i]) alive = false;   // last write wins
            if (alive) {
                const float x = in[row_off + cols[i]];   // L1-hot: row just streamed
                wsum += vals[i];
                dot  += vals[i] * x;
            }
        }

        const double row_loss = (double)(wsum * lse - dot);
        atomicAdd(reinterpret_cast<double*>(&g_acc_bits), row_loss);
        __threadfence();                          // adds visible before ticket
        const unsigned t = atomicAdd(&g_ticket, 1u);
        if (t == (unsigned)(N_ROWS - 1)) {
            // Last block: read-and-reset accumulator atomically, write mean,
            // reset ticket for the next graph replay.
            g_ticket = 0;
            const unsigned long long bits = atomicExch(&g_acc_bits, 0ull);
            const double total = __longlong_as_double((long long)bits);
            out[0] = (float)(total / (double)N_ROWS);
        }
    }
}

extern "C" void kernel_launch(void* const* d_in, const int* in_sizes, int n_in,
                              void* d_out, int out_size) {
    const float* input = (const float*)d_in[0];   // [N, T] fp32
    const float* label = (const float*)d_in[1];   // [N] fp32
    float* out = (float*)d_out;

    loss_kernel<<<N_ROWS, THREADS>>>(input, label, out);
}

// round 13
// speedup vs baseline: 1.0854x; 1.0854x over previous
#include <cuda_runtime.h>
#include <cuda_bf16.h>
#include <math.h>

// Problem shape (fixed by the dataset): input [N, T] fp32, label [N] fp32.
static constexpr int N_ROWS = 8192;
static constexpr int T_COLS = 8192;

static constexpr int THREADS = 256;
static constexpr int VEC = T_COLS / (THREADS * 4);   // 8 float4 per thread per row
static constexpr int GRID = 456;                      // 152 SMs x 3 resident blocks

// Scratch (no cudaMalloc). Zero at process start; RESET by the last block
// each run so graph replays are deterministic.
__device__ unsigned long long g_acc_bits;   // double accumulator, as bits
__device__ unsigned int g_ticket;

__device__ __forceinline__ void load_row(float4 (&v)[VEC],
                                         const float* __restrict__ in,
                                         int row, int tid) {
    const float4* rp = reinterpret_cast<const float4*>(in + (size_t)row * T_COLS);
#pragma unroll
    for (int k = 0; k < VEC; k++) v[k] = rp[tid + k * THREADS];
}

// Full per-row reduction + sparse-target loss. Returns the row loss on tid 0
// (0 elsewhere). Three __syncthreads per call; s_red reuse is protected by
// the trailing barrier.
__device__ __forceinline__ float compute_row(const float4 (&v)[VEC],
                                             const float* __restrict__ in,
                                             const float* __restrict__ label,
                                             int row, int tid,
                                             float* s_red, float* s_max) {
    // Thread-local max (consumes ALL of v -> waits for the full row batch).
    float m = -INFINITY;
#pragma unroll
    for (int k = 0; k < VEC; k++)
        m = fmaxf(m, fmaxf(fmaxf(v[k].x, v[k].y), fmaxf(v[k].z, v[k].w)));
#pragma unroll
    for (int off = 16; off > 0; off >>= 1)
        m = fmaxf(m, __shfl_xor_sync(0xFFFFFFFFu, m, off));
    if ((tid & 31) == 0) s_red[tid >> 5] = m;
    __syncthreads();
    if (tid < 32) {
        float mm = (tid < THREADS / 32) ? s_red[tid] : -INFINITY;
#pragma unroll
        for (int off = 4; off > 0; off >>= 1)
            mm = fmaxf(mm, __shfl_xor_sync(0xFFFFFFFFu, mm, off));
        if (tid == 0) *s_max = mm;
    }
    __syncthreads();
    const float M = *s_max;

    float s = 0.0f;
#pragma unroll
    for (int k = 0; k < VEC; k++) {
        s += __expf(v[k].x - M);
        s += __expf(v[k].y - M);
        s += __expf(v[k].z - M);
        s += __expf(v[k].w - M);
    }
#pragma unroll
    for (int off = 16; off > 0; off >>= 1)
        s += __shfl_xor_sync(0xFFFFFFFFu, s, off);
    if ((tid & 31) == 0) s_red[tid >> 5] = s;
    __syncthreads();

    float loss = 0.0f;
    if (tid < 32) {
        float ss = (tid < THREADS / 32) ? s_red[tid] : 0.0f;
#pragma unroll
        for (int off = 4; off > 0; off >>= 1)
            ss += __shfl_xor_sync(0xFFFFFFFFu, ss, off);
        if (tid == 0) {
            const float lse = M + __logf(ss);

            const float pos = label[row] * (float)T_COLS - 1.0f;
            const int fl = (int)floorf(pos);
            const int ce = (int)ceilf(pos);

            // Replicate reference write ORDER (later writes overwrite earlier).
            int   cols[4];
            float vals[4];
            cols[0] = max(fl - 1, 0);          vals[0] = 0.1f;
            cols[1] = fl;                      vals[1] = (fl >= 1) ? 0.4f : 0.5f;
            cols[2] = min(ce + 1, T_COLS - 1); vals[2] = 0.1f;
            cols[3] = ce;                      vals[3] = (ce < T_COLS - 1) ? 0.4f : 0.5f;

            float wsum = 0.0f, dot = 0.0f;
#pragma unroll
            for (int i = 0; i < 4; i++) {
                bool alive = true;
#pragma unroll
                for (int j = i + 1; j < 4; j++)
                    if (cols[j] == cols[i]) alive = false;   // last write wins
                if (alive) {
                    const float x = in[(size_t)row * T_COLS + cols[i]];  // L2-hot
                    wsum += vals[i];
                    dot  += vals[i] * x;
                }
            }
            loss = wsum * lse - dot;
        }
    }
    __syncthreads();   // protect s_red/s_max for the next call
    return loss;
}

// 3 blocks/SM cap (<=85 regs): two row buffers (64 regs) + scalars fit; the
// explicit load pipeline, not occupancy, hides DRAM latency.
__global__ __launch_bounds__(THREADS, 3)
void loss_kernel(const float* __restrict__ in,
                 const float* __restrict__ label,
                 float* __restrict__ out) {
    __shared__ float s_red[THREADS / 32];
    __shared__ float s_max;

    const int tid = threadIdx.x;
    const int bid = blockIdx.x;

    double acc = 0.0;                 // meaningful on tid 0 only
    float4 a[VEC], b[VEC];

    // Software pipeline over this block's rows: bid, bid+GRID, bid+2*GRID, ...
    // Loads for the NEXT row are issued before the current row is consumed,
    // so each block always has a full 32KB row in flight.
    int r0 = bid;
    load_row(a, in, r0, tid);         // GRID < N_ROWS: always valid
    while (r0 < N_ROWS) {
        const int r1 = r0 + GRID;
        if (r1 < N_ROWS) load_row(b, in, r1, tid);
        {
            const float l = compute_row(a, in, label, r0, tid, s_red, &s_max);
            if (tid == 0) acc += (double)l;
        }
        if (r1 < N_ROWS) {
            const int r2 = r1 + GRID;
            if (r2 < N_ROWS) load_row(a, in, r2, tid);
            const float l = compute_row(b, in, label, r1, tid, s_red, &s_max);
            if (tid == 0) acc += (double)l;
        }
        r0 = r1 + GRID;
    }

    // Per-block result -> global double atomic; last block finalizes.
    if (tid == 0) {
        atomicAdd(reinterpret_cast<double*>(&g_acc_bits), acc);
        __threadfence();
        const unsigned t = atomicAdd(&g_ticket, 1u);
        if (t == (unsigned)(GRID - 1)) {
            g_ticket = 0;                                    // reset for replay
            const unsigned long long bits = atomicExch(&g_acc_bits, 0ull);
            const double total = __longlong_as_double((long long)bits);
            out[0] = (float)(total / (double)N_ROWS);
        }
    }
}

extern "C" void kernel_launch(void* const* d_in, const int* in_sizes, int n_in,
                              void* d_out, int out_size) {
    const float* input = (const float*)d_in[0];   // [N, T] fp32
    const float* label = (const float*)d_in[1];   // [N] fp32
    float* out = (float*)d_out;

    loss_kernel<<<GRID, THREADS>>>(input, label, out);
}